// round 2
// baseline (speedup 1.0000x reference)
#include <cuda_runtime.h>
#include <math.h>

// ---------------------------------------------------------------------------
// GGNN layer: N=50000 nodes, E=600000 edges, D=128.
//   msg  = X @ (W1@W2) + (b1@W2 + b2)            (folded 2-layer linear net)
//   agg  = scatter_add both directions over edges
//   mx   = agg @ gru_kernel  + gru_bias[0]
//   mh   = X   @ gru_rkernel + gru_bias[1]
//   out  = z*X + (1-z)*tanh(xh + r*rh),  z/r = sigmoid(gate sums)
// ---------------------------------------------------------------------------

#define D_DIM 128
#define MAXN 50048

// scratch (device globals: no allocation allowed)
__device__ float g_Wm[D_DIM * D_DIM];          // W1@W2
__device__ float g_bm[D_DIM];                  // b1@W2 + b2
__device__ float g_msg[MAXN * D_DIM];          // X_msg
__device__ float g_agg[MAXN * D_DIM];          // aggregated messages
__device__ float g_mx[MAXN * 3 * D_DIM];       // agg @ gru_kernel + bias0
__device__ float g_mh[MAXN * 3 * D_DIM];       // X @ gru_rkernel + bias1

typedef unsigned long long u64;

__device__ __forceinline__ u64 pack2(float lo, float hi) {
    u64 r; asm("mov.b64 %0, {%1,%2};" : "=l"(r) : "f"(lo), "f"(hi)); return r;
}
__device__ __forceinline__ float2 unpack2(u64 v) {
    float2 r; asm("mov.b64 {%0,%1}, %2;" : "=f"(r.x), "=f"(r.y) : "l"(v)); return r;
}
// packed f32x2 FMA (sm_103a FFMA2) — 2x fp32 FMA throughput vs scalar FFMA
__device__ __forceinline__ void fma2(u64& acc, u64 a, u64 b) {
    asm("fma.rn.f32x2 %0, %1, %2, %0;" : "+l"(acc) : "l"(a), "l"(b));
}

// ---------------------------------------------------------------------------
// SGEMM: C[M, NC] = A[M,128] @ B[128, NC] (+ bias broadcast over rows)
// 128x128 tile per CTA, 256 threads, 8x8 per thread (2x2 quadrants of 4x4),
// BK=8, FFMA2 inner product.
// ---------------------------------------------------------------------------
__device__ __forceinline__ void gemm_body(const float* __restrict__ A,
                                          const float* __restrict__ B,
                                          const float* __restrict__ bias,
                                          float* __restrict__ C,
                                          int M, int NC)
{
    __shared__ float As[8][128];
    __shared__ float Bs[8][128];

    const int tid = threadIdx.x;
    const int tx  = tid & 15;
    const int ty  = tid >> 4;
    const int m0  = blockIdx.x * 128;
    const int n0  = blockIdx.y * 128;

    u64 acc[8][4];
#pragma unroll
    for (int i = 0; i < 8; i++)
#pragma unroll
        for (int j = 0; j < 4; j++) acc[i][j] = 0ull;

    const int arow  = m0 + (tid >> 1);
    const int acol4 = (tid & 1) << 2;
    const int brow  = tid >> 5;
    const int bcol4 = (tid & 31) << 2;

    for (int k0 = 0; k0 < 128; k0 += 8) {
        float4 av = make_float4(0.f, 0.f, 0.f, 0.f);
        if (arow < M)
            av = *(const float4*)(A + (size_t)arow * 128 + k0 + acol4);
        float4 bv = *(const float4*)(B + (size_t)(k0 + brow) * NC + n0 + bcol4);

        __syncthreads();
        As[acol4 + 0][tid >> 1] = av.x;
        As[acol4 + 1][tid >> 1] = av.y;
        As[acol4 + 2][tid >> 1] = av.z;
        As[acol4 + 3][tid >> 1] = av.w;
        *(float4*)&Bs[brow][bcol4] = bv;
        __syncthreads();

#pragma unroll
        for (int kk = 0; kk < 8; kk++) {
            float4 a0 = *(const float4*)&As[kk][ty * 4];
            float4 a1 = *(const float4*)&As[kk][64 + ty * 4];
            float4 b0 = *(const float4*)&Bs[kk][tx * 4];
            float4 b1 = *(const float4*)&Bs[kk][64 + tx * 4];
            u64 bp0 = pack2(b0.x, b0.y);
            u64 bp1 = pack2(b0.z, b0.w);
            u64 bp2 = pack2(b1.x, b1.y);
            u64 bp3 = pack2(b1.z, b1.w);
            float av8[8] = {a0.x, a0.y, a0.z, a0.w, a1.x, a1.y, a1.z, a1.w};
#pragma unroll
            for (int i = 0; i < 8; i++) {
                u64 ap = pack2(av8[i], av8[i]);
                fma2(acc[i][0], ap, bp0);
                fma2(acc[i][1], ap, bp1);
                fma2(acc[i][2], ap, bp2);
                fma2(acc[i][3], ap, bp3);
            }
        }
    }

    float4 bias0 = make_float4(0.f, 0.f, 0.f, 0.f);
    float4 bias1 = bias0;
    if (bias) {
        bias0 = *(const float4*)(bias + n0 + tx * 4);
        bias1 = *(const float4*)(bias + n0 + 64 + tx * 4);
    }

#pragma unroll
    for (int ih = 0; ih < 2; ih++) {
#pragma unroll
        for (int i2 = 0; i2 < 4; i2++) {
            int i = ih * 4 + i2;
            int row = m0 + ih * 64 + ty * 4 + i2;
            if (row < M) {
                float2 p0 = unpack2(acc[i][0]);
                float2 p1 = unpack2(acc[i][1]);
                float2 p2 = unpack2(acc[i][2]);
                float2 p3 = unpack2(acc[i][3]);
                float4 v0 = make_float4(p0.x + bias0.x, p0.y + bias0.y,
                                        p1.x + bias0.z, p1.y + bias0.w);
                float4 v1 = make_float4(p2.x + bias1.x, p2.y + bias1.y,
                                        p3.x + bias1.z, p3.y + bias1.w);
                *(float4*)(C + (size_t)row * NC + n0 + tx * 4)      = v0;
                *(float4*)(C + (size_t)row * NC + n0 + 64 + tx * 4) = v1;
            }
        }
    }
}

// ---- GEMM wrappers (device globals referenced directly; no symbol lookup) --

__global__ void __launch_bounds__(256) k_fold_w(const float* __restrict__ W1,
                                                const float* __restrict__ W2) {
    gemm_body(W1, W2, nullptr, g_Wm, 128, 128);   // Wm = W1@W2
}

__global__ void k_fold_b(const float* __restrict__ b1,
                         const float* __restrict__ W2,
                         const float* __restrict__ b2) {
    int n = threadIdx.x;            // 128 threads
    float s = b2[n];
    for (int k = 0; k < 128; k++) s += b1[k] * W2[k * 128 + n];
    g_bm[n] = s;                    // bm = b1@W2 + b2
}

__global__ void __launch_bounds__(256) k_gemm_msg(const float* __restrict__ X, int M) {
    gemm_body(X, g_Wm, g_bm, g_msg, M, 128);
}

__global__ void __launch_bounds__(256) k_gemm_mx(const float* __restrict__ gk,
                                                 const float* __restrict__ gb, int M) {
    gemm_body(g_agg, gk, gb, g_mx, M, 384);
}

__global__ void __launch_bounds__(256) k_gemm_mh(const float* __restrict__ X,
                                                 const float* __restrict__ grk,
                                                 const float* __restrict__ gb1, int M) {
    gemm_body(X, grk, gb1, g_mh, M, 384);
}

// ---- zero agg -------------------------------------------------------------
__global__ void k_zero(int n4) {
    int i = blockIdx.x * blockDim.x + threadIdx.x;
    if (i < n4) ((float4*)g_agg)[i] = make_float4(0.f, 0.f, 0.f, 0.f);
}

// ---- undirected scatter-add over edges: one warp per edge, both directions.
// 16B vector reductions (red.global.add.v4.f32, sm_90+) -> 4x fewer L2 atomics
__global__ void __launch_bounds__(256) k_scatter(const int* __restrict__ ra,
                                                 const int* __restrict__ rb, int E) {
    int w    = (blockIdx.x * 256 + threadIdx.x) >> 5;
    int lane = threadIdx.x & 31;
    if (w >= E) return;
    int a = ra[w];
    int b = rb[w];
    float4 va = ((const float4*)(g_msg + (size_t)a * 128))[lane];
    float4 vb = ((const float4*)(g_msg + (size_t)b * 128))[lane];
    float* pb = g_agg + (size_t)b * 128 + lane * 4;
    float* pa = g_agg + (size_t)a * 128 + lane * 4;
    asm volatile("red.global.add.v4.f32 [%0], {%1,%2,%3,%4};"
                 :: "l"(pb), "f"(va.x), "f"(va.y), "f"(va.z), "f"(va.w) : "memory");
    asm volatile("red.global.add.v4.f32 [%0], {%1,%2,%3,%4};"
                 :: "l"(pa), "f"(vb.x), "f"(vb.y), "f"(vb.z), "f"(vb.w) : "memory");
}

// ---- fused GRU epilogue ---------------------------------------------------
__global__ void __launch_bounds__(256) k_gru(const float* __restrict__ X,
                                             float* __restrict__ out, int total) {
    int idx = blockIdx.x * 256 + threadIdx.x;
    if (idx >= total) return;
    int node = idx >> 7;
    int c    = idx & 127;
    const float* mx = g_mx + (size_t)node * 384;
    const float* mh = g_mh + (size_t)node * 384;
    float z  = 1.f / (1.f + expf(-(mx[c]       + mh[c])));
    float r  = 1.f / (1.f + expf(-(mx[128 + c] + mh[128 + c])));
    float hh = tanhf(mx[256 + c] + r * mh[256 + c]);
    float x  = X[idx];
    out[idx] = z * x + (1.f - z) * hh;
}

// ---------------------------------------------------------------------------
extern "C" void kernel_launch(void* const* d_in, const int* in_sizes, int n_in,
                              void* d_out, int out_size)
{
    const float* X   = (const float*)d_in[0];
    const int*   ra  = (const int*)  d_in[1];
    const int*   rb  = (const int*)  d_in[2];
    const float* W1  = (const float*)d_in[3];
    const float* b1  = (const float*)d_in[4];
    const float* W2  = (const float*)d_in[5];
    const float* b2  = (const float*)d_in[6];
    const float* gk  = (const float*)d_in[7];
    const float* grk = (const float*)d_in[8];
    const float* gb  = (const float*)d_in[9];

    const int N = in_sizes[0] / D_DIM;
    const int E = in_sizes[1];
    const int mblocks = (N + 127) / 128;

    // weight folding (tiny)
    k_fold_w<<<dim3(1, 1), 256>>>(W1, W2);
    k_fold_b<<<1, 128>>>(b1, W2, b2);

    // zero agg, msg GEMM
    k_zero<<<(N * 32 + 255) / 256, 256>>>(N * 32);
    k_gemm_msg<<<dim3(mblocks, 1), 256>>>(X, N);

    // edge scatter (atomic, L2-resident)
    k_scatter<<<(E + 7) / 8, 256>>>(ra, rb, E);

    // GRU gate GEMMs (mh independent of scatter; mx depends on agg)
    k_gemm_mh<<<dim3(mblocks, 3), 256>>>(X, grk, gb + 384, N);
    k_gemm_mx<<<dim3(mblocks, 3), 256>>>(gk, gb, N);

    // fused elementwise GRU update
    k_gru<<<(N * D_DIM + 255) / 256, 256>>>(X, (float*)d_out, N * D_DIM);
}

// round 4
// speedup vs baseline: 1.0304x; 1.0304x over previous
#include <cuda_runtime.h>
#include <cuda_bf16.h>
#include <math.h>
#include <cstdint>

// ---------------------------------------------------------------------------
// GGNN layer, GB300 via baseline-PTX tensor cores (mma.sync bf16 = HMMA).
//   msg  = X @ (W1@W2) + (b1@W2+b2)
//   agg  = undirected scatter-add over edges (fp32 L2 red.v4)
//   mh   = X   @ gru_rkernel + bias1  ;  mx = agg @ gru_kernel + bias0
//   out  = z*X + (1-z)*tanh(xh + r*rh)
// Precision: A=Ah+Al (bf16), B=Bh+Bl (bf16); D = AhBh + AhBl + AlBh (fp32 acc)
// ---------------------------------------------------------------------------

#define D_DIM 128
#define MAXN  50048

__device__ float g_Wm[D_DIM * D_DIM];            // W1@W2
__device__ float g_bm[D_DIM];                    // b1@W2 + b2
__device__ float g_msg[MAXN * D_DIM];
__device__ float g_agg[MAXN * D_DIM];
__device__ float g_mx[MAXN * 3 * D_DIM];
__device__ float g_mh[MAXN * 3 * D_DIM];
// 7 weight tiles (msg, mh x3, mx x3), each 128(n) x 128(k) bf16 hi/lo,
// stored [n][k] row-major as u32 k-pairs: [j][n][64]
__device__ __align__(16) unsigned int g_BhW[7 * 8192];
__device__ __align__(16) unsigned int g_BlW[7 * 8192];
__device__ float g_biasAll[7 * 128];

// ---------------------------------------------------------------------------
__device__ __forceinline__ uint32_t smem_u32(const void* p) {
    uint32_t a;
    asm("{ .reg .u64 t; cvta.to.shared.u64 t, %1; cvt.u32.u64 %0, t; }"
        : "=r"(a) : "l"(p));
    return a;
}

// split float2 into packed bf16x2 hi + lo
__device__ __forceinline__ void split2(float2 v, uint32_t& hp, uint32_t& lp) {
    asm("cvt.rn.bf16x2.f32 %0, %1, %2;" : "=r"(hp) : "f"(v.y), "f"(v.x));
    float h0 = __uint_as_float(hp << 16);
    float h1 = __uint_as_float(hp & 0xFFFF0000u);
    asm("cvt.rn.bf16x2.f32 %0, %1, %2;" : "=r"(lp) : "f"(v.y - h1), "f"(v.x - h0));
}

__device__ __forceinline__ void ldsm4(uint32_t& r0, uint32_t& r1, uint32_t& r2,
                                      uint32_t& r3, uint32_t addr) {
    asm volatile("ldmatrix.sync.aligned.m8n8.x4.shared.b16 {%0,%1,%2,%3}, [%4];"
                 : "=r"(r0), "=r"(r1), "=r"(r2), "=r"(r3) : "r"(addr));
}

__device__ __forceinline__ void mma16816(float* c, const uint32_t* a,
                                         const uint32_t* b) {
    asm volatile(
        "mma.sync.aligned.m16n8k16.row.col.f32.bf16.bf16.f32 "
        "{%0,%1,%2,%3}, {%4,%5,%6,%7}, {%8,%9}, {%0,%1,%2,%3};"
        : "+f"(c[0]), "+f"(c[1]), "+f"(c[2]), "+f"(c[3])
        : "r"(a[0]), "r"(a[1]), "r"(a[2]), "r"(a[3]), "r"(b[0]), "r"(b[1]));
}

// smem tile layout: 128 rows x 256 bytes (128 bf16). 16B chunks XOR-swizzled.
__device__ __forceinline__ uint32_t swoff(int row, int chunk, int within) {
    return (uint32_t)(row * 256 + ((chunk ^ (row & 7)) << 4) + within);
}

// ---------------------------------------------------------------------------
// weight prep
// ---------------------------------------------------------------------------
__global__ void k_fold_w(const float* __restrict__ W1,
                         const float* __restrict__ W2) {
    __shared__ float row[128];
    int i = blockIdx.x, n = threadIdx.x;
    row[n] = W1[i * 128 + n];
    __syncthreads();
    float s = 0.f;
#pragma unroll 8
    for (int k = 0; k < 128; k++) s += row[k] * W2[k * 128 + n];
    g_Wm[i * 128 + n] = s;
}

__global__ void k_fold_b(const float* __restrict__ b1,
                         const float* __restrict__ W2,
                         const float* __restrict__ b2) {
    int n = threadIdx.x;
    float s = b2[n];
    for (int k = 0; k < 128; k++) s += b1[k] * W2[k * 128 + n];
    g_bm[n] = s;
}

// build split bf16 weights in [n][k] layout + biases. 7 blocks x 128 thr.
__global__ void k_convB(const float* __restrict__ gk,
                        const float* __restrict__ grk,
                        const float* __restrict__ gb) {
    int j = blockIdx.x, n = threadIdx.x;
    const float* src; int NCw, c0; const float* bsrc;
    if (j == 0)      { src = g_Wm; NCw = 128; c0 = 0;             bsrc = g_bm; }
    else if (j < 4)  { src = grk;  NCw = 384; c0 = (j - 1) * 128; bsrc = gb + 384 + c0; }
    else             { src = gk;   NCw = 384; c0 = (j - 4) * 128; bsrc = gb + c0; }

    unsigned int* bh = g_BhW + (size_t)j * 8192 + n * 64;
    unsigned int* bl = g_BlW + (size_t)j * 8192 + n * 64;
    for (int k = 0; k < 128; k += 2) {
        float2 v = make_float2(src[(size_t)k * NCw + c0 + n],
                               src[(size_t)(k + 1) * NCw + c0 + n]);
        uint32_t hp, lp; split2(v, hp, lp);
        bh[k >> 1] = hp;
        bl[k >> 1] = lp;
    }
    g_biasAll[j * 128 + n] = bsrc[n];
}

// ---------------------------------------------------------------------------
// bf16 split-precision GEMM: 128x128 tile/CTA, K=128 in smem, 8 warps.
// warp tile 32(M) x 64(N). j = jbase + blockIdx.y selects B/bias/dst.
// ---------------------------------------------------------------------------
#define SM_AH 0
#define SM_AL 32768
#define SM_BH 65536
#define SM_BL 98304
#define SM_TOTAL 131072

__global__ void __launch_bounds__(256)
k_mmagemm(const float* __restrict__ A, int M, int jbase) {
    extern __shared__ char smem[];
    const uint32_t sb = smem_u32(smem);
    const int tid = threadIdx.x, wid = tid >> 5, lane = tid & 31;
    const int j  = jbase + blockIdx.y;
    const int m0 = blockIdx.x * 128;

    // ---- copy pre-split B tiles with swizzle (16B chunks) ----
    {
        const uint4* sh = (const uint4*)g_BhW + (size_t)j * 2048;
        const uint4* sl = (const uint4*)g_BlW + (size_t)j * 2048;
#pragma unroll
        for (int i = 0; i < 8; i++) {
            int c = tid + i * 256;            // 0..2047
            int row = c >> 4, col = c & 15;
            uint32_t d = swoff(row, col, 0);
            *(uint4*)(smem + SM_BH + d) = sh[c];
            *(uint4*)(smem + SM_BL + d) = sl[c];
        }
    }

    // ---- load + split A tile ----
    {
        const float* Asrc = A ? A : g_agg;
        int r = tid >> 1, h = tid & 1;
        int grow = m0 + r;
        bool valid = grow < M;
        const float2* arow = (const float2*)(Asrc + (size_t)grow * 128) + h * 32;
#pragma unroll 8
        for (int q = 0; q < 32; q++) {
            float2 v = valid ? arow[q] : make_float2(0.f, 0.f);
            uint32_t hp, lp; split2(v, hp, lp);
            int idx4 = h * 32 + q;            // u32 index within row
            uint32_t d = swoff(r, idx4 >> 2, (idx4 & 3) * 4);
            *(uint32_t*)(smem + SM_AH + d) = hp;
            *(uint32_t*)(smem + SM_AL + d) = lp;
        }
    }
    __syncthreads();

    // ---- compute ----
    const int warp_m = wid >> 1;              // 0..3
    const int warp_n = wid & 1;               // 0..1
    float acc[2][8][4];
#pragma unroll
    for (int mf = 0; mf < 2; mf++)
#pragma unroll
        for (int nf = 0; nf < 8; nf++)
#pragma unroll
            for (int q = 0; q < 4; q++) acc[mf][nf][q] = 0.f;

    // ldmatrix row/chunk patterns (absolute tile rows)
    const int a_row = warp_m * 32 + (lane & 15);          // + mf*16
    const int a_hik = lane >> 4;                          // chunk half
    const int b_row = warp_n * 64 + (lane & 7) + ((lane >> 4) << 3);  // + p*16
    const int b_hik = (lane >> 3) & 1;

#pragma unroll
    for (int s = 0; s < 8; s++) {
        uint32_t ah[2][4], al[2][4], bh[16], bl[16];
#pragma unroll
        for (int mf = 0; mf < 2; mf++) {
            uint32_t off = swoff(a_row + mf * 16, s * 2 + a_hik, 0);
            ldsm4(ah[mf][0], ah[mf][1], ah[mf][2], ah[mf][3], sb + SM_AH + off);
            ldsm4(al[mf][0], al[mf][1], al[mf][2], al[mf][3], sb + SM_AL + off);
        }
#pragma unroll
        for (int p = 0; p < 4; p++) {
            uint32_t off = swoff(b_row + p * 16, s * 2 + b_hik, 0);
            ldsm4(bh[p * 4 + 0], bh[p * 4 + 1], bh[p * 4 + 2], bh[p * 4 + 3],
                  sb + SM_BH + off);
            ldsm4(bl[p * 4 + 0], bl[p * 4 + 1], bl[p * 4 + 2], bl[p * 4 + 3],
                  sb + SM_BL + off);
        }
        // ldsm x4 matrix order for B: (n0-7,k0-7),(n0-7,k8-15),(n8-15,k0-7),(n8-15,k8-15)
#pragma unroll
        for (int mf = 0; mf < 2; mf++)
#pragma unroll
            for (int nf = 0; nf < 8; nf++) {
                const uint32_t* bhf = &bh[(nf >> 1) * 4 + (nf & 1) * 2];
                const uint32_t* blf = &bl[(nf >> 1) * 4 + (nf & 1) * 2];
                mma16816(acc[mf][nf], ah[mf], bhf);
                mma16816(acc[mf][nf], ah[mf], blf);
                mma16816(acc[mf][nf], al[mf], bhf);
            }
    }

    // ---- epilogue: bias + store fp32 ----
    float* dst; int NC, c0;
    if (j == 0)      { dst = g_msg; NC = 128; c0 = 0; }
    else if (j < 4)  { dst = g_mh;  NC = 384; c0 = (j - 1) * 128; }
    else             { dst = g_mx;  NC = 384; c0 = (j - 4) * 128; }
    const float* bias = g_biasAll + j * 128;

    const int tr = lane >> 2, tc = (lane & 3) * 2;
#pragma unroll
    for (int mf = 0; mf < 2; mf++) {
        int row0 = m0 + warp_m * 32 + mf * 16 + tr;
#pragma unroll
        for (int nf = 0; nf < 8; nf++) {
            int col = warp_n * 64 + nf * 8 + tc;
            float bx = bias[col], by = bias[col + 1];
            if (row0 < M)
                *(float2*)(dst + (size_t)row0 * NC + c0 + col) =
                    make_float2(acc[mf][nf][0] + bx, acc[mf][nf][1] + by);
            if (row0 + 8 < M)
                *(float2*)(dst + (size_t)(row0 + 8) * NC + c0 + col) =
                    make_float2(acc[mf][nf][2] + bx, acc[mf][nf][3] + by);
        }
    }
}

// ---------------------------------------------------------------------------
// zero / scatter / gru (unchanged from R2 pass)
// ---------------------------------------------------------------------------
__global__ void k_zero(int n4) {
    int i = blockIdx.x * blockDim.x + threadIdx.x;
    if (i < n4) ((float4*)g_agg)[i] = make_float4(0.f, 0.f, 0.f, 0.f);
}

__global__ void __launch_bounds__(256) k_scatter(const int* __restrict__ ra,
                                                 const int* __restrict__ rb, int E) {
    int w    = (blockIdx.x * 256 + threadIdx.x) >> 5;
    int lane = threadIdx.x & 31;
    if (w >= E) return;
    int a = ra[w];
    int b = rb[w];
    float4 va = ((const float4*)(g_msg + (size_t)a * 128))[lane];
    float4 vb = ((const float4*)(g_msg + (size_t)b * 128))[lane];
    float* pb = g_agg + (size_t)b * 128 + lane * 4;
    float* pa = g_agg + (size_t)a * 128 + lane * 4;
    asm volatile("red.global.add.v4.f32 [%0], {%1,%2,%3,%4};"
                 :: "l"(pb), "f"(va.x), "f"(va.y), "f"(va.z), "f"(va.w) : "memory");
    asm volatile("red.global.add.v4.f32 [%0], {%1,%2,%3,%4};"
                 :: "l"(pa), "f"(vb.x), "f"(vb.y), "f"(vb.z), "f"(vb.w) : "memory");
}

__global__ void __launch_bounds__(256) k_gru(const float* __restrict__ X,
                                             float* __restrict__ out, int total) {
    int idx = blockIdx.x * 256 + threadIdx.x;
    if (idx >= total) return;
    int node = idx >> 7;
    int c    = idx & 127;
    const float* mx = g_mx + (size_t)node * 384;
    const float* mh = g_mh + (size_t)node * 384;
    float z  = 1.f / (1.f + expf(-(mx[c]       + mh[c])));
    float r  = 1.f / (1.f + expf(-(mx[128 + c] + mh[128 + c])));
    float hh = tanhf(mx[256 + c] + r * mh[256 + c]);
    float x  = X[idx];
    out[idx] = z * x + (1.f - z) * hh;
}

// ---------------------------------------------------------------------------
extern "C" void kernel_launch(void* const* d_in, const int* in_sizes, int n_in,
                              void* d_out, int out_size)
{
    const float* X   = (const float*)d_in[0];
    const int*   ra  = (const int*)  d_in[1];
    const int*   rb  = (const int*)  d_in[2];
    const float* W1  = (const float*)d_in[3];
    const float* b1  = (const float*)d_in[4];
    const float* W2  = (const float*)d_in[5];
    const float* b2  = (const float*)d_in[6];
    const float* gk  = (const float*)d_in[7];
    const float* grk = (const float*)d_in[8];
    const float* gb  = (const float*)d_in[9];

    const int N = in_sizes[0] / D_DIM;
    const int E = in_sizes[1];
    const int mblocks = (N + 127) / 128;

    cudaFuncSetAttribute(k_mmagemm, cudaFuncAttributeMaxDynamicSharedMemorySize,
                         SM_TOTAL);

    // weight folding + split-bf16 weight build (tiny)
    k_fold_w<<<128, 128>>>(W1, W2);
    k_fold_b<<<1, 128>>>(b1, W2, b2);
    k_convB<<<7, 128>>>(gk, grk, gb);

    k_zero<<<(N * 32 + 255) / 256, 256>>>(N * 32);

    // msg (j=0) + mh (j=1..3): A = X
    k_mmagemm<<<dim3(mblocks, 4), 256, SM_TOTAL>>>(X, N, 0);

    // edge scatter into g_agg
    k_scatter<<<(E + 7) / 8, 256>>>(ra, rb, E);

    // mx (j=4..6): A = agg
    k_mmagemm<<<dim3(mblocks, 3), 256, SM_TOTAL>>>(nullptr, N, 4);

    // fused GRU update
    k_gru<<<(N * D_DIM + 255) / 256, 256>>>(X, (float*)d_out, N * D_DIM);
}

// round 5
// speedup vs baseline: 1.2315x; 1.1952x over previous
#include <cuda_runtime.h>
#include <cuda_bf16.h>
#include <math.h>
#include <cstdint>

// ---------------------------------------------------------------------------
// GGNN layer, GB300. HMMA (mma.sync bf16) split-precision GEMMs with
// cp.async double-buffered K-streaming, 2 CTAs/SM.
//   msg = X @ (W1@W2) + (b1@W2+b2); agg = undirected scatter-add;
//   mh = X@grk + b; mx = agg@gk + b; out = z*X + (1-z)*tanh(xh + r*rh)
// Precision: A=Ah+Al, B=Bh+Bl (bf16); D = AhBh + AlBh + AhBl (fp32 acc)
// ---------------------------------------------------------------------------

#define D_DIM 128
#define MAXN  50048   // = 391 * 128, exact tile padding for N=50000

__device__ float g_Wm[D_DIM * D_DIM];
__device__ float g_bm[D_DIM];
__device__ float g_msg[MAXN * D_DIM];
__device__ float g_agg[MAXN * D_DIM];
__device__ float g_mx[MAXN * 3 * D_DIM];
__device__ float g_mh[MAXN * 3 * D_DIM];
// pre-split A operands (bf16 pairs, row = 64 u32 = 128 bf16)
__device__ __align__(16) unsigned int g_Xh[MAXN * 64];
__device__ __align__(16) unsigned int g_Xl[MAXN * 64];
__device__ __align__(16) unsigned int g_Gh[MAXN * 64];
__device__ __align__(16) unsigned int g_Gl[MAXN * 64];
// 7 weight tiles (msg, mh x3, mx x3) [n][k] bf16 pairs
__device__ __align__(16) unsigned int g_BhW[7 * 8192];
__device__ __align__(16) unsigned int g_BlW[7 * 8192];
__device__ float g_biasAll[7 * 128];

// ---------------------------------------------------------------------------
__device__ __forceinline__ uint32_t smem_u32(const void* p) {
    uint32_t a;
    asm("{ .reg .u64 t; cvta.to.shared.u64 t, %1; cvt.u32.u64 %0, t; }"
        : "=r"(a) : "l"(p));
    return a;
}
__device__ __forceinline__ void split2(float2 v, uint32_t& hp, uint32_t& lp) {
    asm("cvt.rn.bf16x2.f32 %0, %1, %2;" : "=r"(hp) : "f"(v.y), "f"(v.x));
    float h0 = __uint_as_float(hp << 16);
    float h1 = __uint_as_float(hp & 0xFFFF0000u);
    asm("cvt.rn.bf16x2.f32 %0, %1, %2;" : "=r"(lp) : "f"(v.y - h1), "f"(v.x - h0));
}
__device__ __forceinline__ void ldsm4(uint32_t& r0, uint32_t& r1, uint32_t& r2,
                                      uint32_t& r3, uint32_t addr) {
    asm volatile("ldmatrix.sync.aligned.m8n8.x4.shared.b16 {%0,%1,%2,%3}, [%4];"
                 : "=r"(r0), "=r"(r1), "=r"(r2), "=r"(r3) : "r"(addr));
}
__device__ __forceinline__ void mma16816(float* c, const uint32_t* a,
                                         const uint32_t* b) {
    asm volatile(
        "mma.sync.aligned.m16n8k16.row.col.f32.bf16.bf16.f32 "
        "{%0,%1,%2,%3}, {%4,%5,%6,%7}, {%8,%9}, {%0,%1,%2,%3};"
        : "+f"(c[0]), "+f"(c[1]), "+f"(c[2]), "+f"(c[3])
        : "r"(a[0]), "r"(a[1]), "r"(a[2]), "r"(a[3]), "r"(b[0]), "r"(b[1]));
}
__device__ __forceinline__ void cpa16(uint32_t dst, const void* src) {
    asm volatile("cp.async.cg.shared.global [%0], [%1], 16;"
                 :: "r"(dst), "l"(src));
}

// ---------------------------------------------------------------------------
// weight prep
// ---------------------------------------------------------------------------
__global__ void k_fold_w(const float* __restrict__ W1,
                         const float* __restrict__ W2) {
    __shared__ float row[128];
    int i = blockIdx.x, n = threadIdx.x;
    row[n] = W1[i * 128 + n];
    __syncthreads();
    float s = 0.f;
#pragma unroll 8
    for (int k = 0; k < 128; k++) s += row[k] * W2[k * 128 + n];
    g_Wm[i * 128 + n] = s;
}
__global__ void k_fold_b(const float* __restrict__ b1,
                         const float* __restrict__ W2,
                         const float* __restrict__ b2) {
    int n = threadIdx.x;
    float s = b2[n];
    for (int k = 0; k < 128; k++) s += b1[k] * W2[k * 128 + n];
    g_bm[n] = s;
}

// blocks 0-6: build split weight tiles [n][k]; blocks 7+: split X rows.
__global__ void __launch_bounds__(256)
k_prep(const float* __restrict__ X, const float* __restrict__ gk,
       const float* __restrict__ grk, const float* __restrict__ gb, int N) {
    int b = blockIdx.x, tid = threadIdx.x;
    if (b < 7) {
        int j = b, n = tid & 127, half = tid >> 7;
        const float* src; int NCw, c0; const float* bsrc;
        if (j == 0)      { src = g_Wm; NCw = 128; c0 = 0;             bsrc = g_bm; }
        else if (j < 4)  { src = grk;  NCw = 384; c0 = (j - 1) * 128; bsrc = gb + 384 + c0; }
        else             { src = gk;   NCw = 384; c0 = (j - 4) * 128; bsrc = gb + c0; }
        unsigned int* bh = g_BhW + (size_t)j * 8192 + n * 64;
        unsigned int* bl = g_BlW + (size_t)j * 8192 + n * 64;
        for (int k = half * 64; k < half * 64 + 64; k += 2) {
            float2 v = make_float2(src[(size_t)k * NCw + c0 + n],
                                   src[(size_t)(k + 1) * NCw + c0 + n]);
            uint32_t hp, lp; split2(v, hp, lp);
            bh[k >> 1] = hp;
            bl[k >> 1] = lp;
        }
        if (half == 0) g_biasAll[j * 128 + n] = bsrc[n];
    } else {
        int r = (b - 7) * 64 + (tid >> 2);
        int q = tid & 3;
        uint4 hi[4], lo[4];
        if (r < N) {
            const float2* xr = (const float2*)(X + (size_t)r * 128) + q * 16;
#pragma unroll
            for (int g = 0; g < 4; g++) {
                uint32_t h0, l0, h1, l1, h2, l2, h3, l3;
                split2(xr[g * 4 + 0], h0, l0);
                split2(xr[g * 4 + 1], h1, l1);
                split2(xr[g * 4 + 2], h2, l2);
                split2(xr[g * 4 + 3], h3, l3);
                hi[g] = make_uint4(h0, h1, h2, h3);
                lo[g] = make_uint4(l0, l1, l2, l3);
            }
        } else {
#pragma unroll
            for (int g = 0; g < 4; g++) {
                hi[g] = make_uint4(0, 0, 0, 0);
                lo[g] = make_uint4(0, 0, 0, 0);
            }
        }
        uint4* dh = (uint4*)(g_Xh + (size_t)r * 64 + q * 16);
        uint4* dl = (uint4*)(g_Xl + (size_t)r * 64 + q * 16);
#pragma unroll
        for (int g = 0; g < 4; g++) { dh[g] = hi[g]; dl[g] = lo[g]; }
    }
}

// split agg -> g_Gh/g_Gl (after scatter); zero-pads tail rows
__global__ void __launch_bounds__(256)
k_splitAgg(int N) {
    int r = blockIdx.x * 64 + (threadIdx.x >> 2);
    int q = threadIdx.x & 3;
    uint4 hi[4], lo[4];
    if (r < N) {
        const float2* xr = (const float2*)(g_agg + (size_t)r * 128) + q * 16;
#pragma unroll
        for (int g = 0; g < 4; g++) {
            uint32_t h0, l0, h1, l1, h2, l2, h3, l3;
            split2(xr[g * 4 + 0], h0, l0);
            split2(xr[g * 4 + 1], h1, l1);
            split2(xr[g * 4 + 2], h2, l2);
            split2(xr[g * 4 + 3], h3, l3);
            hi[g] = make_uint4(h0, h1, h2, h3);
            lo[g] = make_uint4(l0, l1, l2, l3);
        }
    } else {
#pragma unroll
        for (int g = 0; g < 4; g++) {
            hi[g] = make_uint4(0, 0, 0, 0);
            lo[g] = make_uint4(0, 0, 0, 0);
        }
    }
    uint4* dh = (uint4*)(g_Gh + (size_t)r * 64 + q * 16);
    uint4* dl = (uint4*)(g_Gl + (size_t)r * 64 + q * 16);
#pragma unroll
    for (int g = 0; g < 4; g++) { dh[g] = hi[g]; dl[g] = lo[g]; }
}

// ---------------------------------------------------------------------------
// K-streamed split-bf16 HMMA GEMM. 128x128 tile/CTA, BK=32, 2-stage cp.async
// pipeline, 64KB smem -> 2 CTAs/SM. Stage row layout: 128B = 8x16B chunks,
// chunks 0-3 = hi k, 4-7 = lo k; physical chunk = logical ^ (row&7).
// ---------------------------------------------------------------------------
#define SM_TOTAL 65536

__global__ void __launch_bounds__(256, 2)
k_mmagemm(int useAgg, int jbase) {
    extern __shared__ char smem[];
    const uint32_t sb = smem_u32(smem);
    const int tid = threadIdx.x, wid = tid >> 5, lane = tid & 31;
    const int j  = jbase + blockIdx.y;
    const int m0 = blockIdx.x * 128;

    const unsigned int* Ah = useAgg ? g_Gh : g_Xh;
    const unsigned int* Al = useAgg ? g_Gl : g_Xl;
    const char* aBase;
    const char* bBase;
    {
        const int r = tid >> 1, h = tid & 1;
        aBase = (const char*)(h ? Al : Ah) + ((size_t)(m0 + r)) * 256;
        bBase = (const char*)(h ? g_BlW : g_BhW) + (size_t)j * 32768
                + (size_t)r * 256;
    }
    const int fr = tid >> 1, fh = tid & 1, frx = fr & 7;

#define FILL(d, s) do {                                                   \
        uint32_t _ad = sb + (d) * 32768 + fr * 128;                       \
        uint32_t _bd = _ad + 16384;                                       \
        const char* _as = aBase + (s) * 64;                               \
        const char* _bs = bBase + (s) * 64;                               \
        _Pragma("unroll")                                                 \
        for (int c = 0; c < 4; c++) {                                     \
            uint32_t sw = (uint32_t)(((fh * 4 + c) ^ frx) << 4);          \
            cpa16(_ad + sw, _as + c * 16);                                \
            cpa16(_bd + sw, _bs + c * 16);                                \
        }                                                                 \
        asm volatile("cp.async.commit_group;" ::: "memory");              \
    } while (0)

    FILL(0, 0);
    FILL(1, 1);

    const int warp_m = wid >> 1, warp_n = wid & 1;
    float acc[2][8][4];
#pragma unroll
    for (int mf = 0; mf < 2; mf++)
#pragma unroll
        for (int nf = 0; nf < 8; nf++)
#pragma unroll
            for (int q = 0; q < 4; q++) acc[mf][nf][q] = 0.f;

    const int a_row  = warp_m * 32 + (lane & 15);
    const int a_sel  = lane >> 4;
    const int b_row  = warp_n * 64 + (lane & 7) + ((lane >> 4) << 3);
    const int b_sel  = (lane >> 3) & 1;

#pragma unroll
    for (int s = 0; s < 4; s++) {
        if (s < 3) asm volatile("cp.async.wait_group 1;" ::: "memory");
        else       asm volatile("cp.async.wait_group 0;" ::: "memory");
        __syncthreads();
        const uint32_t saA = sb + (s & 1) * 32768;
        const uint32_t saB = saA + 16384;

#pragma unroll
        for (int t = 0; t < 2; t++) {
            uint32_t ah[2][4], al[2][4], bfr[16];
#pragma unroll
            for (int mf = 0; mf < 2; mf++) {
                int row = a_row + mf * 16, rx = row & 7, lc = 2 * t + a_sel;
                uint32_t base = saA + row * 128;
                ldsm4(ah[mf][0], ah[mf][1], ah[mf][2], ah[mf][3],
                      base + ((lc ^ rx) << 4));
                ldsm4(al[mf][0], al[mf][1], al[mf][2], al[mf][3],
                      base + (((lc + 4) ^ rx) << 4));
            }
#pragma unroll
            for (int p = 0; p < 4; p++) {
                int row = b_row + p * 16, rx = row & 7, lc = 2 * t + b_sel;
                ldsm4(bfr[p * 4], bfr[p * 4 + 1], bfr[p * 4 + 2], bfr[p * 4 + 3],
                      saB + row * 128 + ((lc ^ rx) << 4));
            }
#pragma unroll
            for (int mf = 0; mf < 2; mf++)
#pragma unroll
                for (int nf = 0; nf < 8; nf++) {
                    const uint32_t* bs = &bfr[(nf >> 1) * 4 + (nf & 1) * 2];
                    mma16816(acc[mf][nf], ah[mf], bs);   // Ah*Bh
                    mma16816(acc[mf][nf], al[mf], bs);   // Al*Bh
                }
#pragma unroll
            for (int p = 0; p < 4; p++) {
                int row = b_row + p * 16, rx = row & 7, lc = 2 * t + b_sel + 4;
                ldsm4(bfr[p * 4], bfr[p * 4 + 1], bfr[p * 4 + 2], bfr[p * 4 + 3],
                      saB + row * 128 + ((lc ^ rx) << 4));
            }
#pragma unroll
            for (int mf = 0; mf < 2; mf++)
#pragma unroll
                for (int nf = 0; nf < 8; nf++) {
                    const uint32_t* bs = &bfr[(nf >> 1) * 4 + (nf & 1) * 2];
                    mma16816(acc[mf][nf], ah[mf], bs);   // Ah*Bl
                }
        }
        __syncthreads();
        if (s < 2) FILL(s & 1, s + 2);
    }
#undef FILL

    // epilogue: bias + fp32 store (buffers padded to tile grid; no guards)
    float* dst; int NC, c0;
    if (j == 0)      { dst = g_msg; NC = 128; c0 = 0; }
    else if (j < 4)  { dst = g_mh;  NC = 384; c0 = (j - 1) * 128; }
    else             { dst = g_mx;  NC = 384; c0 = (j - 4) * 128; }
    const float* bias = g_biasAll + j * 128;

    const int tr = lane >> 2, tc = (lane & 3) * 2;
#pragma unroll
    for (int mf = 0; mf < 2; mf++) {
        int row0 = m0 + warp_m * 32 + mf * 16 + tr;
#pragma unroll
        for (int nf = 0; nf < 8; nf++) {
            int col = warp_n * 64 + nf * 8 + tc;
            float bx = bias[col], by = bias[col + 1];
            *(float2*)(dst + (size_t)row0 * NC + c0 + col) =
                make_float2(acc[mf][nf][0] + bx, acc[mf][nf][1] + by);
            *(float2*)(dst + (size_t)(row0 + 8) * NC + c0 + col) =
                make_float2(acc[mf][nf][2] + bx, acc[mf][nf][3] + by);
        }
    }
}

// ---------------------------------------------------------------------------
__global__ void k_zero(int n4) {
    int i = blockIdx.x * blockDim.x + threadIdx.x;
    if (i < n4) ((float4*)g_agg)[i] = make_float4(0.f, 0.f, 0.f, 0.f);
}

__global__ void __launch_bounds__(256) k_scatter(const int* __restrict__ ra,
                                                 const int* __restrict__ rb, int E) {
    int w    = (blockIdx.x * 256 + threadIdx.x) >> 5;
    int lane = threadIdx.x & 31;
    if (w >= E) return;
    int a = ra[w];
    int b = rb[w];
    float4 va = ((const float4*)(g_msg + (size_t)a * 128))[lane];
    float4 vb = ((const float4*)(g_msg + (size_t)b * 128))[lane];
    float* pb = g_agg + (size_t)b * 128 + lane * 4;
    float* pa = g_agg + (size_t)a * 128 + lane * 4;
    asm volatile("red.global.add.v4.f32 [%0], {%1,%2,%3,%4};"
                 :: "l"(pb), "f"(va.x), "f"(va.y), "f"(va.z), "f"(va.w) : "memory");
    asm volatile("red.global.add.v4.f32 [%0], {%1,%2,%3,%4};"
                 :: "l"(pa), "f"(vb.x), "f"(vb.y), "f"(vb.z), "f"(vb.w) : "memory");
}

__device__ __forceinline__ float sgm(float x) { return 1.f / (1.f + expf(-x)); }

__global__ void __launch_bounds__(256) k_gru(const float* __restrict__ X,
                                             float* __restrict__ out, int n4) {
    int i = blockIdx.x * 256 + threadIdx.x;
    if (i >= n4) return;
    int node = i >> 5, c = i & 31;
    const float4* mx = (const float4*)g_mx + (size_t)node * 96;
    const float4* mh = (const float4*)g_mh + (size_t)node * 96;
    float4 xz = mx[c],      rz = mh[c];
    float4 xr = mx[32 + c], rr = mh[32 + c];
    float4 xh = mx[64 + c], rh = mh[64 + c];
    float4 x  = ((const float4*)X)[i];
    float4 o;
    {
        float z = sgm(xz.x + rz.x), r = sgm(xr.x + rr.x);
        o.x = z * x.x + (1.f - z) * tanhf(xh.x + r * rh.x);
    }
    {
        float z = sgm(xz.y + rz.y), r = sgm(xr.y + rr.y);
        o.y = z * x.y + (1.f - z) * tanhf(xh.y + r * rh.y);
    }
    {
        float z = sgm(xz.z + rz.z), r = sgm(xr.z + rr.z);
        o.z = z * x.z + (1.f - z) * tanhf(xh.z + r * rh.z);
    }
    {
        float z = sgm(xz.w + rz.w), r = sgm(xr.w + rr.w);
        o.w = z * x.w + (1.f - z) * tanhf(xh.w + r * rh.w);
    }
    ((float4*)out)[i] = o;
}

// ---------------------------------------------------------------------------
extern "C" void kernel_launch(void* const* d_in, const int* in_sizes, int n_in,
                              void* d_out, int out_size)
{
    const float* X   = (const float*)d_in[0];
    const int*   ra  = (const int*)  d_in[1];
    const int*   rb  = (const int*)  d_in[2];
    const float* W1  = (const float*)d_in[3];
    const float* b1  = (const float*)d_in[4];
    const float* W2  = (const float*)d_in[5];
    const float* b2  = (const float*)d_in[6];
    const float* gk  = (const float*)d_in[7];
    const float* grk = (const float*)d_in[8];
    const float* gb  = (const float*)d_in[9];

    const int N = in_sizes[0] / D_DIM;
    const int E = in_sizes[1];
    const int mblocks = (N + 127) / 128;
    const int sblocks = (mblocks * 128) / 64;   // split-row blocks (=782)

    cudaFuncSetAttribute(k_mmagemm, cudaFuncAttributeMaxDynamicSharedMemorySize,
                         SM_TOTAL);

    // 1-3: weight folding + split weights + split X
    k_fold_w<<<128, 128>>>(W1, W2);
    k_fold_b<<<1, 128>>>(b1, W2, b2);
    k_prep<<<7 + sblocks, 256>>>(X, gk, grk, gb, N);

    // 4 (profiled): msg (j=0) + mh (j=1..3), A = split X
    k_mmagemm<<<dim3(mblocks, 4), 256, SM_TOTAL>>>(0, 0);

    // 5-7: zero agg, scatter, split agg
    k_zero<<<(N * 32 + 255) / 256, 256>>>(N * 32);
    k_scatter<<<(E + 7) / 8, 256>>>(ra, rb, E);
    k_splitAgg<<<sblocks, 256>>>(N);

    // 8: mx (j=4..6), A = split agg
    k_mmagemm<<<dim3(mblocks, 3), 256, SM_TOTAL>>>(1, 4);

    // 9: fused GRU update
    k_gru<<<(N * 32 + 255) / 256, 256>>>(X, (float*)d_out, N * 32);
}

// round 6
// speedup vs baseline: 1.5017x; 1.2194x over previous
#include <cuda_runtime.h>
#include <cuda_bf16.h>
#include <math.h>
#include <cstdint>

// ---------------------------------------------------------------------------
// GGNN layer, GB300. Split-bf16 HMMA GEMMs, A as global fragment-major
// operands (no A smem, no in-loop barriers), persistent CTAs with B-in-smem.
//   msg = X @ (W1@W2) + (b1@W2+b2); agg = undirected scatter-add;
//   mh = X@grk + b; mx = agg@gk + b; out = z*X + (1-z)*tanh(xh + r*rh)
// Precision: A=Ah+Al, B=Bh+Bl (bf16); D = AhBh + AlBh + AhBl (fp32 acc)
// ---------------------------------------------------------------------------

#define D_DIM 128
#define MAXN  50048            // 391*128 — exact tile padding
#define MBTOT (MAXN / 16)      // 3128 16-row m-blocks

__device__ float g_Wm[D_DIM * D_DIM];
__device__ float g_bm[D_DIM];
__device__ float g_msg[MAXN * D_DIM];
__device__ float g_agg[MAXN * D_DIM];
__device__ float g_mx[MAXN * 3 * D_DIM];
__device__ float g_mh[MAXN * 3 * D_DIM];
// A operands in mma-fragment order: [mb][ks][lane] -> {hi uint4, lo uint4}
__device__ uint4 g_XF[MBTOT * 8 * 32 * 2];
__device__ uint4 g_GF[MBTOT * 8 * 32 * 2];
// 7 weight tiles (msg, mh x3, mx x3) [n][k] bf16 pairs (linear rows, 256B)
__device__ __align__(16) unsigned int g_BhW[7 * 8192];
__device__ __align__(16) unsigned int g_BlW[7 * 8192];
__device__ float g_biasAll[7 * 128];

// ---------------------------------------------------------------------------
__device__ __forceinline__ uint32_t smem_u32(const void* p) {
    uint32_t a;
    asm("{ .reg .u64 t; cvta.to.shared.u64 t, %1; cvt.u32.u64 %0, t; }"
        : "=r"(a) : "l"(p));
    return a;
}
__device__ __forceinline__ void split2(float2 v, uint32_t& hp, uint32_t& lp) {
    asm("cvt.rn.bf16x2.f32 %0, %1, %2;" : "=r"(hp) : "f"(v.y), "f"(v.x));
    float h0 = __uint_as_float(hp << 16);
    float h1 = __uint_as_float(hp & 0xFFFF0000u);
    asm("cvt.rn.bf16x2.f32 %0, %1, %2;" : "=r"(lp) : "f"(v.y - h1), "f"(v.x - h0));
}
__device__ __forceinline__ void ldsm4(uint32_t& r0, uint32_t& r1, uint32_t& r2,
                                      uint32_t& r3, uint32_t addr) {
    asm volatile("ldmatrix.sync.aligned.m8n8.x4.shared.b16 {%0,%1,%2,%3}, [%4];"
                 : "=r"(r0), "=r"(r1), "=r"(r2), "=r"(r3) : "r"(addr));
}
__device__ __forceinline__ void mma16816(float* c, const uint32_t* a,
                                         const uint32_t* b) {
    asm volatile(
        "mma.sync.aligned.m16n8k16.row.col.f32.bf16.bf16.f32 "
        "{%0,%1,%2,%3}, {%4,%5,%6,%7}, {%8,%9}, {%0,%1,%2,%3};"
        : "+f"(c[0]), "+f"(c[1]), "+f"(c[2]), "+f"(c[3])
        : "r"(a[0]), "r"(a[1]), "r"(a[2]), "r"(a[3]), "r"(b[0]), "r"(b[1]));
}
__device__ __forceinline__ void cpa16(uint32_t dst, const void* src) {
    asm volatile("cp.async.cg.shared.global [%0], [%1], 16;"
                 :: "r"(dst), "l"(src));
}

// ---------------------------------------------------------------------------
// weight prep
// ---------------------------------------------------------------------------
__global__ void k_fold_w(const float* __restrict__ W1,
                         const float* __restrict__ W2) {
    __shared__ float row[128];
    int i = blockIdx.x, n = threadIdx.x;
    row[n] = W1[i * 128 + n];
    __syncthreads();
    float s = 0.f;
#pragma unroll 8
    for (int k = 0; k < 128; k++) s += row[k] * W2[k * 128 + n];
    g_Wm[i * 128 + n] = s;
}
__global__ void k_fold_b(const float* __restrict__ b1,
                         const float* __restrict__ W2,
                         const float* __restrict__ b2) {
    int n = threadIdx.x;
    float s = b2[n];
    for (int k = 0; k < 128; k++) s += b1[k] * W2[k * 128 + n];
    g_bm[n] = s;
}

// split weight tiles [n][k] (hi/lo) + biases: 7 blocks x 256 threads
__global__ void __launch_bounds__(256)
k_prepW(const float* __restrict__ gk, const float* __restrict__ grk,
        const float* __restrict__ gb) {
    int j = blockIdx.x, tid = threadIdx.x;
    int n = tid & 127, half = tid >> 7;
    const float* src; int NCw, c0; const float* bsrc;
    if (j == 0)      { src = g_Wm; NCw = 128; c0 = 0;             bsrc = g_bm; }
    else if (j < 4)  { src = grk;  NCw = 384; c0 = (j - 1) * 128; bsrc = gb + 384 + c0; }
    else             { src = gk;   NCw = 384; c0 = (j - 4) * 128; bsrc = gb + c0; }
    unsigned int* bh = g_BhW + (size_t)j * 8192 + n * 64;
    unsigned int* bl = g_BlW + (size_t)j * 8192 + n * 64;
    for (int k = half * 64; k < half * 64 + 64; k += 2) {
        float2 v = make_float2(src[(size_t)k * NCw + c0 + n],
                               src[(size_t)(k + 1) * NCw + c0 + n]);
        uint32_t hp, lp; split2(v, hp, lp);
        bh[k >> 1] = hp;
        bl[k >> 1] = lp;
    }
    if (half == 0) g_biasAll[j * 128 + n] = bsrc[n];
}

// ---------------------------------------------------------------------------
// split X or agg into mma-fragment-major hi/lo bf16 pairs.
// block = one 16-row m-block; warp w = k16 step w; lane owns a0..a3 slots.
// ---------------------------------------------------------------------------
__global__ void __launch_bounds__(256)
k_split(const float* __restrict__ X, int useAgg, int N) {
    int mb = blockIdx.x;
    int ks = threadIdx.x >> 5, lane = threadIdx.x & 31;
    const float* src = useAgg ? g_agg : X;
    uint4* dstF = useAgg ? g_GF : g_XF;

    int r0 = mb * 16 + (lane >> 2), r1 = r0 + 8;
    int k0 = ks * 16 + (lane & 3) * 2;
    float2 z2 = make_float2(0.f, 0.f);
    float2 v00 = (r0 < N) ? *(const float2*)(src + (size_t)r0 * 128 + k0)     : z2;
    float2 v01 = (r0 < N) ? *(const float2*)(src + (size_t)r0 * 128 + k0 + 8) : z2;
    float2 v10 = (r1 < N) ? *(const float2*)(src + (size_t)r1 * 128 + k0)     : z2;
    float2 v11 = (r1 < N) ? *(const float2*)(src + (size_t)r1 * 128 + k0 + 8) : z2;

    uint32_t h0, l0, h1, l1, h2, l2, h3, l3;
    split2(v00, h0, l0);   // a0 = (r0, k0)
    split2(v10, h1, l1);   // a1 = (r1, k0)
    split2(v01, h2, l2);   // a2 = (r0, k0+8)
    split2(v11, h3, l3);   // a3 = (r1, k0+8)

    size_t f = ((size_t)(mb * 8 + ks) * 32 + lane) * 2;
    dstF[f]     = make_uint4(h0, h1, h2, h3);
    dstF[f + 1] = make_uint4(l0, l1, l2, l3);
}

// ---------------------------------------------------------------------------
// persistent split-bf16 HMMA GEMM. CTA: loads B tile (64KB hi+lo) once, then
// loops m-tiles barrier-free: A frags via LDG, B frags via ldsm.
// smem B: hi rows 256B at r*256 (region 0), lo at +32768; chunk c phys = c^(r&7).
// ---------------------------------------------------------------------------
#define SM_TOTAL 65536

__global__ void __launch_bounds__(256, 2)
k_mmagemm(int useAgg, int jbase, int mtiles) {
    extern __shared__ char smem[];
    const uint32_t sb = smem_u32(smem);
    const int tid = threadIdx.x, wid = tid >> 5, lane = tid & 31;
    const int j = jbase + blockIdx.y;

    // ---- load B tile once ----
    {
        int r = tid >> 1, h = tid & 1;
        const char* s = (const char*)(h ? g_BlW : g_BhW)
                        + (size_t)j * 32768 + (size_t)r * 256;
        uint32_t drow = sb + h * 32768 + r * 256;
        uint32_t rx = (uint32_t)(r & 7);
#pragma unroll
        for (int c = 0; c < 16; c++)
            cpa16(drow + (((uint32_t)c ^ rx) << 4), s + c * 16);
        asm volatile("cp.async.commit_group;" ::: "memory");
        asm volatile("cp.async.wait_group 0;" ::: "memory");
        __syncthreads();
    }

    const int warp_m = wid >> 1, warp_n = wid & 1;
    const int b_row = warp_n * 64 + (lane & 7) + ((lane >> 4) << 3);
    const uint32_t b_rx = (uint32_t)(b_row & 7);
    const int b_sel = (lane >> 3) & 1;
    const uint32_t bBaseHi = sb + b_row * 256;
    const uint32_t bBaseLo = bBaseHi + 32768;

    // dst / bias per j
    float* dst; int NC, c0;
    if (j == 0)      { dst = g_msg; NC = 128; c0 = 0; }
    else if (j < 4)  { dst = g_mh;  NC = 384; c0 = (j - 1) * 128; }
    else             { dst = g_mx;  NC = 384; c0 = (j - 4) * 128; }
    const float* biasG = g_biasAll + j * 128;
    const int tr = lane >> 2, tc = (lane & 3) * 2;
    float bx[8], by[8];
#pragma unroll
    for (int nf = 0; nf < 8; nf++) {
        int col = warp_n * 64 + nf * 8 + tc;
        bx[nf] = biasG[col];
        by[nf] = biasG[col + 1];
    }

    const uint4* AF = useAgg ? g_GF : g_XF;

    for (int mt = blockIdx.x; mt < mtiles; mt += gridDim.x) {
        float acc[2][8][4];
#pragma unroll
        for (int mf = 0; mf < 2; mf++)
#pragma unroll
            for (int nf = 0; nf < 8; nf++)
#pragma unroll
                for (int q = 0; q < 4; q++) acc[mf][nf][q] = 0.f;

        const int mbBase = mt * 8 + warp_m * 2;
        const uint4* a0 = AF + (((size_t)mbBase * 8) * 32 + lane) * 2;
        const uint4* a1 = AF + (((size_t)(mbBase + 1) * 8) * 32 + lane) * 2;

#pragma unroll
        for (int s = 0; s < 8; s++) {
            uint4 ahv0 = a0[s * 64], alv0 = a0[s * 64 + 1];
            uint4 ahv1 = a1[s * 64], alv1 = a1[s * 64 + 1];
            const uint32_t* ah0 = &ahv0.x;
            const uint32_t* al0 = &alv0.x;
            const uint32_t* ah1 = &ahv1.x;
            const uint32_t* al1 = &alv1.x;

            uint32_t bfr[16];
            uint32_t lc = (uint32_t)(2 * s + b_sel);
#pragma unroll
            for (int p = 0; p < 4; p++)
                ldsm4(bfr[p * 4], bfr[p * 4 + 1], bfr[p * 4 + 2], bfr[p * 4 + 3],
                      bBaseHi + p * 16 * 256 + ((lc ^ b_rx) << 4));
#pragma unroll
            for (int nf = 0; nf < 8; nf++) {
                const uint32_t* bs = &bfr[(nf >> 1) * 4 + (nf & 1) * 2];
                mma16816(acc[0][nf], ah0, bs);    // Ah*Bh
                mma16816(acc[1][nf], ah1, bs);
                mma16816(acc[0][nf], al0, bs);    // Al*Bh
                mma16816(acc[1][nf], al1, bs);
            }
#pragma unroll
            for (int p = 0; p < 4; p++)
                ldsm4(bfr[p * 4], bfr[p * 4 + 1], bfr[p * 4 + 2], bfr[p * 4 + 3],
                      bBaseLo + p * 16 * 256 + ((lc ^ b_rx) << 4));
#pragma unroll
            for (int nf = 0; nf < 8; nf++) {
                const uint32_t* bs = &bfr[(nf >> 1) * 4 + (nf & 1) * 2];
                mma16816(acc[0][nf], ah0, bs);    // Ah*Bl
                mma16816(acc[1][nf], ah1, bs);
            }
        }

        // epilogue
        const int m0 = mt * 128;
#pragma unroll
        for (int mf = 0; mf < 2; mf++) {
            int row0 = m0 + warp_m * 32 + mf * 16 + tr;
#pragma unroll
            for (int nf = 0; nf < 8; nf++) {
                int col = warp_n * 64 + nf * 8 + tc;
                *(float2*)(dst + (size_t)row0 * NC + c0 + col) =
                    make_float2(acc[mf][nf][0] + bx[nf], acc[mf][nf][1] + by[nf]);
                *(float2*)(dst + (size_t)(row0 + 8) * NC + c0 + col) =
                    make_float2(acc[mf][nf][2] + bx[nf], acc[mf][nf][3] + by[nf]);
            }
        }
    }
}

// ---------------------------------------------------------------------------
__global__ void k_zero(int n4) {
    int i = blockIdx.x * blockDim.x + threadIdx.x;
    if (i < n4) ((float4*)g_agg)[i] = make_float4(0.f, 0.f, 0.f, 0.f);
}

__global__ void __launch_bounds__(256) k_scatter(const int* __restrict__ ra,
                                                 const int* __restrict__ rb, int E) {
    int w    = (blockIdx.x * 256 + threadIdx.x) >> 5;
    int lane = threadIdx.x & 31;
    if (w >= E) return;
    int a = ra[w];
    int b = rb[w];
    float4 va = ((const float4*)(g_msg + (size_t)a * 128))[lane];
    float4 vb = ((const float4*)(g_msg + (size_t)b * 128))[lane];
    float* pb = g_agg + (size_t)b * 128 + lane * 4;
    float* pa = g_agg + (size_t)a * 128 + lane * 4;
    asm volatile("red.global.add.v4.f32 [%0], {%1,%2,%3,%4};"
                 :: "l"(pb), "f"(va.x), "f"(va.y), "f"(va.z), "f"(va.w) : "memory");
    asm volatile("red.global.add.v4.f32 [%0], {%1,%2,%3,%4};"
                 :: "l"(pa), "f"(vb.x), "f"(vb.y), "f"(vb.z), "f"(vb.w) : "memory");
}

__device__ __forceinline__ float sgm(float x) { return 1.f / (1.f + expf(-x)); }

__global__ void __launch_bounds__(256) k_gru(const float* __restrict__ X,
                                             float* __restrict__ out, int n4) {
    int i = blockIdx.x * 256 + threadIdx.x;
    if (i >= n4) return;
    int node = i >> 5, c = i & 31;
    const float4* mx = (const float4*)g_mx + (size_t)node * 96;
    const float4* mh = (const float4*)g_mh + (size_t)node * 96;
    float4 xz = mx[c],      rz = mh[c];
    float4 xr = mx[32 + c], rr = mh[32 + c];
    float4 xh = mx[64 + c], rh = mh[64 + c];
    float4 x  = ((const float4*)X)[i];
    float4 o;
    { float z = sgm(xz.x + rz.x), r = sgm(xr.x + rr.x);
      o.x = z * x.x + (1.f - z) * tanhf(xh.x + r * rh.x); }
    { float z = sgm(xz.y + rz.y), r = sgm(xr.y + rr.y);
      o.y = z * x.y + (1.f - z) * tanhf(xh.y + r * rh.y); }
    { float z = sgm(xz.z + rz.z), r = sgm(xr.z + rr.z);
      o.z = z * x.z + (1.f - z) * tanhf(xh.z + r * rh.z); }
    { float z = sgm(xz.w + rz.w), r = sgm(xr.w + rr.w);
      o.w = z * x.w + (1.f - z) * tanhf(xh.w + r * rh.w); }
    ((float4*)out)[i] = o;
}

// ---------------------------------------------------------------------------
extern "C" void kernel_launch(void* const* d_in, const int* in_sizes, int n_in,
                              void* d_out, int out_size)
{
    const float* X   = (const float*)d_in[0];
    const int*   ra  = (const int*)  d_in[1];
    const int*   rb  = (const int*)  d_in[2];
    const float* W1  = (const float*)d_in[3];
    const float* b1  = (const float*)d_in[4];
    const float* W2  = (const float*)d_in[5];
    const float* b2  = (const float*)d_in[6];
    const float* gk  = (const float*)d_in[7];
    const float* grk = (const float*)d_in[8];
    const float* gb  = (const float*)d_in[9];

    const int N = in_sizes[0] / D_DIM;
    const int E = in_sizes[1];
    const int mtiles = (N + 127) / 128;          // 391
    const int mbtot  = mtiles * 8;               // 3128

    cudaFuncSetAttribute(k_mmagemm, cudaFuncAttributeMaxDynamicSharedMemorySize,
                         SM_TOTAL);

    // weight folding + splits
    k_fold_w<<<128, 128>>>(W1, W2);
    k_fold_b<<<1, 128>>>(b1, W2, b2);
    k_prepW<<<7, 256>>>(gk, grk, gb);
    k_zero<<<(N * 32 + 255) / 256, 256>>>(N * 32);
    k_split<<<mbtot, 256>>>(X, 0, N);

    // msg (j=0) + mh (j=1..3): persistent, 2 CTAs/SM
    k_mmagemm<<<dim3(74, 4), 256, SM_TOTAL>>>(0, 0, mtiles);

    // scatter + split agg
    k_scatter<<<(E + 7) / 8, 256>>>(ra, rb, E);
    k_split<<<mbtot, 256>>>(X, 1, N);

    // mx (j=4..6)
    k_mmagemm<<<dim3(98, 3), 256, SM_TOTAL>>>(1, 4, mtiles);

    // fused GRU update
    k_gru<<<(N * 32 + 255) / 256, 256>>>(X, (float*)d_out, N * 32);
}